// round 2
// baseline (speedup 1.0000x reference)
#include <cuda_runtime.h>
#include <cstdint>

// Problem constants (fixed by the reference)
#define M_DIM 8192
#define N_DIM 8192
#define C_DIM 80

// Precomputed result rows: R[c][n] = base[n] - pre_cls[n][c]
// out[m][n] is then simply R[gt[m]][n]  (a pure gather-broadcast copy).
__device__ float g_R[C_DIM * N_DIM];   // 80 * 8192 * 4B = 2.6 MB (L2-resident)

// ---------------------------------------------------------------------------
// Kernel A: build R. Coalesced float4 loads of pre_cls, shared-tile transpose,
// per-row stable softplus sum, subtraction folded in. ~2-3 us.
// ---------------------------------------------------------------------------
#define TN 64            // n-rows per block
#define SPAD 84          // padded row stride in shared (84*4=336B, 16B aligned)

__global__ __launch_bounds__(256)
void build_R_kernel(const float* __restrict__ pre)
{
    __shared__ float S[TN * SPAD];     // S[n][c], padded rows
    __shared__ float base_sm[TN];

    const int tid = threadIdx.x;
    const int n0  = blockIdx.x * TN;

    // Coalesced load: 64 rows x 80 floats = 1280 float4 (contiguous region).
    // 80 % 4 == 0, so each float4 stays within one n-row (c..c+3).
    const float4* src = (const float4*)(pre + (size_t)n0 * C_DIM);
    for (int i = tid; i < TN * C_DIM / 4; i += 256) {
        float4 v = src[i];
        int l = 4 * i;
        int n = l / C_DIM;
        int c = l % C_DIM;               // multiple of 4 -> 16B-aligned STS
        *(float4*)&S[n * SPAD + c] = v;
    }
    __syncthreads();

    // Per-row softplus sum (numerically stable).
    if (tid < TN) {
        float s = 0.0f;
#pragma unroll
        for (int c = 0; c < C_DIM; ++c) {
            float x = S[tid * SPAD + c];
            s += fmaxf(x, 0.0f) + log1pf(__expf(-fabsf(x)));
        }
        base_sm[tid] = s;
    }
    __syncthreads();

    // Write R[c][n0+k] = base[k] - S[k][c], coalesced in k.
    for (int j = tid; j < C_DIM * TN; j += 256) {
        int c = j / TN;
        int k = j % TN;
        g_R[(size_t)c * N_DIM + n0 + k] = base_sm[k] - S[k * SPAD + c];
    }
}

// ---------------------------------------------------------------------------
// Kernel B: out[m][:] = R[gt[m]][:], streamed as TMA bulk stores from SMEM.
// Each block owns one 512-float n-chunk and an m-split. Phase 1 copies the
// 80x512 R slice into shared (160 KB). Phase 2 issues one
// cp.async.bulk.global.shared::cta of 2048B per m-row — no L1, no registers,
// no L2 read traffic in the 268 MB store stream.
// ---------------------------------------------------------------------------
#define CH      512                      // floats per n-chunk (2048 B stores)
#define NCHUNK  (N_DIM / CH)             // 16
#define SPLITM  9                        // 16*9 = 144 blocks = 1 wave
#define SMEM_B  (C_DIM * CH * 4)         // 163840 B dynamic shared

extern __shared__ float Rs[];            // Rs[c][CH], unpadded (TMA-read only)

__global__ __launch_bounds__(256)
void store_out_kernel(const int* __restrict__ gt, float* __restrict__ out)
{
    const int tid = threadIdx.x;
    const int n0  = blockIdx.x * CH;

    // Phase 1: copy R chunk (80 rows x 512 floats) into shared, coalesced.
    {
        const float4* src = (const float4*)(g_R + n0);   // row c at +c*(N/4)
        float4*       dst = (float4*)Rs;
        for (int i = tid; i < C_DIM * (CH / 4); i += 256) {
            int c = i / (CH / 4);
            int k = i % (CH / 4);
            dst[c * (CH / 4) + k] = src[(size_t)c * (N_DIM / 4) + k];
        }
    }
    __syncthreads();
    // Make generic-proxy SMEM writes visible to the async (TMA) proxy.
    asm volatile("fence.proxy.async.shared::cta;" ::: "memory");

    uint32_t sbase;
    asm("{ .reg .u64 t; cvta.to.shared.u64 t, %1; cvt.u32.u64 %0, t; }"
        : "=r"(sbase) : "l"((void*)Rs));

    const int mb = (M_DIM * (int)blockIdx.y) / SPLITM;
    const int me = (M_DIM * ((int)blockIdx.y + 1)) / SPLITM;

    // Phase 2: one 2 KB bulk store per m-row, issued across all 256 threads.
    const uint32_t nbytes = CH * 4;   // 2048
    for (int m = mb + tid; m < me; m += 256) {
        int g = __ldg(&gt[m]);
        uint32_t saddr = sbase + (uint32_t)g * nbytes;
        const float* gdst = out + (size_t)m * N_DIM + n0;
        asm volatile(
            "cp.async.bulk.global.shared::cta.bulk_group [%0], [%1], %2;"
            :: "l"(gdst), "r"(saddr), "r"(nbytes) : "memory");
    }
    // Per-thread bulk group: drain before the block (and its SMEM) retires.
    asm volatile("cp.async.bulk.commit_group;" ::: "memory");
    asm volatile("cp.async.bulk.wait_group 0;" ::: "memory");
    __syncthreads();
}

// ---------------------------------------------------------------------------
extern "C" void kernel_launch(void* const* d_in, const int* in_sizes, int n_in,
                              void* d_out, int out_size)
{
    const int*   gt  = (const int*)d_in[0];      // gt_kind_ind [M]
    const float* pre = (const float*)d_in[1];    // pre_cls [N, C]
    float*       out = (float*)d_out;            // [M, N] f32

    // Idempotent; not a stream op, safe under graph capture.
    cudaFuncSetAttribute(store_out_kernel,
                         cudaFuncAttributeMaxDynamicSharedMemorySize, SMEM_B);

    build_R_kernel<<<N_DIM / TN, 256>>>(pre);

    dim3 grid(NCHUNK, SPLITM);
    store_out_kernel<<<grid, 256, SMEM_B>>>(gt, out);
}

// round 4
// speedup vs baseline: 1.0617x; 1.0617x over previous
#include <cuda_runtime.h>
#include <cstdint>

#define M_DIM 8192
#define N_DIM 8192
#define C_DIM 80
#define CAP   1024          // per-class m-list capacity (mean 102, huge margin)

// Scratch
__device__ float g_R[C_DIM * N_DIM];    // R[c][n] = base[n] - pre[n][c]  (2.6 MB)
__device__ int   g_list[C_DIM * CAP];   // m-indices per class
__device__ int   g_cnt[C_DIM];

// ---------------------------------------------------------------------------
// Kernel A: build R. Coalesced float4 loads, shared transpose, softplus with
// 4 threads per n-row (20 c's each).
// ---------------------------------------------------------------------------
#define TN   64
#define SPAD 84

__global__ __launch_bounds__(256)
void build_R_kernel(const float* __restrict__ pre)
{
    __shared__ float S[TN * SPAD];
    __shared__ float psum[TN * 4];
    __shared__ float base_sm[TN];

    const int tid = threadIdx.x;
    const int n0  = blockIdx.x * TN;

    // Coalesced load of 64 rows x 80 floats (contiguous 20 KB region).
    const float4* src = (const float4*)(pre + (size_t)n0 * C_DIM);
    for (int i = tid; i < TN * C_DIM / 4; i += 256) {
        float4 v = src[i];
        int l = 4 * i;
        *(float4*)&S[(l / C_DIM) * SPAD + (l % C_DIM)] = v;
    }
    __syncthreads();

    // Softplus partial sums: 4 threads per row, 20 c's each.
    {
        int r = tid & 63;
        int q = tid >> 6;
        float s = 0.0f;
#pragma unroll
        for (int c = q * 20; c < q * 20 + 20; ++c) {
            float x = S[r * SPAD + c];
            s += fmaxf(x, 0.0f) + log1pf(__expf(-fabsf(x)));
        }
        psum[q * TN + r] = s;
    }
    __syncthreads();
    if (tid < TN)
        base_sm[tid] = psum[tid] + psum[TN + tid] + psum[2 * TN + tid] + psum[3 * TN + tid];
    __syncthreads();

    // R[c][n0+k] = base[k] - S[k][c], coalesced in k.
    for (int j = tid; j < C_DIM * TN; j += 256) {
        int c = j >> 6;
        int k = j & 63;
        g_R[(size_t)c * N_DIM + n0 + k] = base_sm[k] - S[k * SPAD + c];
    }
}

// ---------------------------------------------------------------------------
// Kernel A2: bucket m-indices by class. One block per class scans gt
// (32 KB, L2-resident after first block touches it). Order within a bucket is
// arbitrary (smem atomic) but the final output is order-independent.
// ---------------------------------------------------------------------------
__global__ __launch_bounds__(256)
void bucketize_kernel(const int* __restrict__ gt)
{
    __shared__ int scnt;
    const int g = blockIdx.x;
    if (threadIdx.x == 0) scnt = 0;
    __syncthreads();

    for (int i = threadIdx.x; i < M_DIM; i += 256) {
        if (__ldg(&gt[i]) == g) {
            int p = atomicAdd(&scnt, 1);
            if (p < CAP) g_list[g * CAP + p] = i;
        }
    }
    __syncthreads();
    if (threadIdx.x == 0) g_cnt[g] = min(scnt, CAP);
}

// ---------------------------------------------------------------------------
// Kernel B: replicate R[g] chunk (held in ONE register float4 per thread) to
// every m in class g's bucket. Zero read traffic in the 256 MB store stream.
// grid = (N/1024 n-chunks, 80 classes, SPLIT m-splits)
// ---------------------------------------------------------------------------
#define CH    1024                 // floats per n-chunk (256 thr * float4)
#define NCH   (N_DIM / CH)         // 8
#define SPLIT 2

__global__ __launch_bounds__(256)
void gather_store_kernel(float* __restrict__ out)
{
    __shared__ int sm[CAP];

    const int tid = threadIdx.x;
    const int g   = blockIdx.y;
    const int n0  = blockIdx.x * CH;
    const int s   = blockIdx.z;

    const int cnt = g_cnt[g];
    const int mb  = cnt * s / SPLIT;
    const int me  = cnt * (s + 1) / SPLIT;
    const int len = me - mb;

    for (int i = tid; i < len; i += 256)
        sm[i] = g_list[g * CAP + mb + i];

    // The block's chunk of R[g]: one float4 per thread, loaded once.
    const float4 v = *(const float4*)&g_R[(size_t)g * N_DIM + n0 + tid * 4];
    __syncthreads();

    for (int j = 0; j < len; ++j) {
        int m = sm[j];
        __stcs((float4*)(out + (size_t)m * N_DIM + n0) + tid, v);
    }
}

// ---------------------------------------------------------------------------
extern "C" void kernel_launch(void* const* d_in, const int* in_sizes, int n_in,
                              void* d_out, int out_size)
{
    const int*   gt  = (const int*)d_in[0];
    const float* pre = (const float*)d_in[1];
    float*       out = (float*)d_out;

    bucketize_kernel<<<C_DIM, 256>>>(gt);
    build_R_kernel<<<N_DIM / TN, 256>>>(pre);

    dim3 grid(NCH, C_DIM, SPLIT);
    gather_store_kernel<<<grid, 256>>>(out);
}

// round 6
// speedup vs baseline: 1.2420x; 1.1698x over previous
#include <cuda_runtime.h>
#include <cstdint>

#define M_DIM 8192
#define N_DIM 8192
#define C_DIM 80

// Precomputed result rows: R[c][n] = base[n] - pre_cls[n][c]   (2.6 MB, L2-resident)
// out[m][:] is then simply R[gt[m]][:]  (gather-broadcast copy).
__device__ float g_R[C_DIM * N_DIM];

// ---------------------------------------------------------------------------
// Kernel A: build R. Coalesced float4 loads, shared transpose, softplus with
// 4 threads per n-row (20 c's each). ~3 us.
// ---------------------------------------------------------------------------
#define TN   64
#define SPAD 84

__global__ __launch_bounds__(256)
void build_R_kernel(const float* __restrict__ pre)
{
    __shared__ float S[TN * SPAD];
    __shared__ float psum[TN * 4];
    __shared__ float base_sm[TN];

    const int tid = threadIdx.x;
    const int n0  = blockIdx.x * TN;

    // Coalesced load of 64 rows x 80 floats (contiguous 20 KB region).
    const float4* src = (const float4*)(pre + (size_t)n0 * C_DIM);
    for (int i = tid; i < TN * C_DIM / 4; i += 256) {
        float4 v = src[i];
        int l = 4 * i;
        *(float4*)&S[(l / C_DIM) * SPAD + (l % C_DIM)] = v;
    }
    __syncthreads();

    // Softplus partial sums: 4 threads per row, 20 c's each.
    {
        int r = tid & 63;
        int q = tid >> 6;
        float s = 0.0f;
#pragma unroll
        for (int c = q * 20; c < q * 20 + 20; ++c) {
            float x = S[r * SPAD + c];
            s += fmaxf(x, 0.0f) + log1pf(__expf(-fabsf(x)));
        }
        psum[q * TN + r] = s;
    }
    __syncthreads();
    if (tid < TN)
        base_sm[tid] = psum[tid] + psum[TN + tid] + psum[2 * TN + tid] + psum[3 * TN + tid];
    __syncthreads();

    // R[c][n0+k] = base[k] - S[k][c], coalesced in k.
    for (int j = tid; j < C_DIM * TN; j += 256) {
        int c = j >> 6;
        int k = j & 63;
        g_R[(size_t)c * N_DIM + n0 + k] = base_sm[k] - S[k * SPAD + c];
    }
}

// ---------------------------------------------------------------------------
// Kernel B: out[m][n] = R[gt[m]][n].
// 256 threads x float4 along n (1024 floats/block), 16 m-rows per block.
// Reads hit L2 on the 2.6 MB g_R and BYPASS L1 (__ldcg) so L1 wavefronts are
// reserved for the store stream; 16 independent LDG.128->STG.128 pairs per
// thread give deep store MLP. Streaming stores (.cs) keep the 256 MB output
// from polluting L2.
// ---------------------------------------------------------------------------
#define BTHREADS 256
#define MROWS    16
#define N4       (N_DIM / 4)     // 2048 float4 per row

__global__ __launch_bounds__(BTHREADS)
void out_kernel(const int* __restrict__ gt, float4* __restrict__ out)
{
    const int n4 = blockIdx.x * BTHREADS + threadIdx.x;  // float4 index along n
    const int m0 = blockIdx.y * MROWS;

    __shared__ int sg[MROWS];
    if (threadIdx.x < MROWS) sg[threadIdx.x] = __ldg(&gt[m0 + threadIdx.x]);
    __syncthreads();

#pragma unroll
    for (int r = 0; r < MROWS; ++r) {
        const float4 v = __ldcg((const float4*)(g_R + (size_t)sg[r] * N_DIM) + n4);
        __stcs(&out[(size_t)(m0 + r) * N4 + n4], v);
    }
}

// ---------------------------------------------------------------------------
extern "C" void kernel_launch(void* const* d_in, const int* in_sizes, int n_in,
                              void* d_out, int out_size)
{
    const int*   gt  = (const int*)d_in[0];      // gt_kind_ind [M]
    const float* pre = (const float*)d_in[1];    // pre_cls [N, C]
    float4*      out = (float4*)d_out;           // [M, N] f32

    build_R_kernel<<<N_DIM / TN, 256>>>(pre);

    dim3 grid(N4 / BTHREADS, M_DIM / MROWS);     // (8, 512)
    out_kernel<<<grid, BTHREADS>>>(gt, out);
}